// round 13
// baseline (speedup 1.0000x reference)
#include <cuda_runtime.h>
#include <cuda_fp16.h>
#include <cstdint>

#define B_SZ 8192
#define L_SZ 64
#define EMB  64
#define HID  128
#define G3   384
#define OUTD 128
#define NVAL 1000

__device__ float g_tab[NVAL * G3];      // xg table, PERMUTED within 16-chunks (fp32, L2-hot)
__device__ float g_Wih_t[EMB * G3];
__device__ float g_cbias[G3];
__device__ uint32_t g_Bf[8 * 8 * 32 * 12];  // Whh fp16 B-fragments, 96KB
__device__ uint32_t g_Of[8 * 32 * 32];      // Wout fp16 B-fragments, 32KB

__device__ __forceinline__ float ftanh_fast(float x) {
    float r;
    asm("tanh.approx.f32 %0, %1;" : "=f"(r) : "f"(x));
    return r;
}
__device__ __forceinline__ float fsig_fast(float x) {
    return fmaf(0.5f, ftanh_fast(0.5f * x), 0.5f);
}
__device__ __forceinline__ uint32_t packh2(float lo, float hi) {
    __half2 h = __floats2half2_rn(lo, hi);
    return *reinterpret_cast<uint32_t*>(&h);
}
__device__ __forceinline__ void hmma(float* d, const uint32_t* a, uint32_t b0, uint32_t b1) {
    asm volatile("mma.sync.aligned.m16n8k16.row.col.f32.f16.f16.f32 "
        "{%0,%1,%2,%3}, {%4,%5,%6,%7}, {%8,%9}, {%0,%1,%2,%3};"
        : "+f"(d[0]), "+f"(d[1]), "+f"(d[2]), "+f"(d[3])
        : "r"(a[0]), "r"(a[1]), "r"(a[2]), "r"(a[3]), "r"(b0), "r"(b1));
}
__device__ __forceinline__ int pperm(int o) {
    return 4 * ((o & 7) >> 1) + (((o >> 3) & 1) << 1) + (o & 1);
}

// ---------------- prep: fragment images ----------------
__global__ void prep_kernel(const float* __restrict__ Wih, const float* __restrict__ Whh,
                            const float* __restrict__ bih, const float* __restrict__ bhh,
                            const float* __restrict__ Wout) {
    int i = blockIdx.x * blockDim.x + threadIdx.x;
    if (i < EMB * G3) { int k = i / G3, gj = i % G3; g_Wih_t[i] = Wih[gj * EMB + k]; }
    if (i < G3) g_cbias[i] = bih[i] + (i < 2 * HID ? bhh[i] : 0.0f);
    if (i < G3 * HID) {
        int gj = i / HID, k = i % HID;
        uint16_t hb = __half_as_ushort(__float2half_rn(Whh[i]));
        int gate = gj >> 7, jr = gj & 127;
        int jc = jr >> 4, nt = (jr >> 3) & 1, nl = jr & 7;
        int kc = k >> 4, kk = k & 15;
        int breg = kk >> 3, q = (kk & 7) >> 1, hs = kk & 1;
        int T = nl * 4 + q, f = gate * 2 + nt;
        int u = ((jc * 8 + kc) * 32 + T) * 12 + f * 2 + breg;
        ((uint16_t*)g_Bf)[u * 2 + hs] = hb;
    }
    if (i < OUTD * HID) {
        int o = i / HID, k = i % HID;
        uint16_t hb = __half_as_ushort(__float2half_rn(Wout[i]));
        int f = o >> 3, nl = o & 7;
        int kc = k >> 4, kk = k & 15;
        int breg = kk >> 3, q = (kk & 7) >> 1, hs = kk & 1;
        int T = nl * 4 + q;
        int u = (kc * 32 + T) * 32 + f * 2 + breg;
        ((uint16_t*)g_Of)[u * 2 + hs] = hb;
    }
}

__global__ void table_kernel(const float* __restrict__ embed) {
    __shared__ float es[EMB];
    const int v = blockIdx.x, gj = threadIdx.x;
    if (gj < EMB) es[gj] = embed[v * EMB + gj];
    __syncthreads();
    float acc = 0.0f;
    #pragma unroll 8
    for (int k = 0; k < EMB; k++) acc = fmaf(es[k], g_Wih_t[k * G3 + gj], acc);
    const int gate = gj >> 7, rest = gj & 127, chunk = rest >> 4, o = rest & 15;
    g_tab[v * G3 + gate * 128 + chunk * 16 + pperm(o)] = acc + g_cbias[gj];
}

// ---------------- GRU: 4-way N-split, 4 warps/SMSP, quad named-barrier h-exchange ----------------
#define NTH 512
#define EXCH_U32 32896
#define GRU_SMEM ((EXCH_U32 + 8192) * 4)   // 164352 bytes
__global__ __launch_bounds__(NTH, 1) void gru_kernel(const int* __restrict__ x,
                                                     const float* __restrict__ bhh,
                                                     const float* __restrict__ bout,
                                                     float* __restrict__ out) {
    extern __shared__ uint32_t sm[];
    uint32_t* Bs = sm;                      // 24576 u32 (96KB)
    uint32_t* Os = sm + 24576;              // 8192 u32 (32KB)
    float* bns = (float*)(sm + 32768);      // 128 floats, permuted bhh_n
    uint4* exch = (uint4*)(sm + EXCH_U32);  // [parity][warp][lane][slot] = 2x16x32x2 uint4
    const int tid = threadIdx.x;
    {
        uint4* d = (uint4*)sm;
        const uint4* s1 = (const uint4*)g_Bf;
        for (int i = tid; i < 6144; i += NTH) d[i] = s1[i];
        const uint4* s2 = (const uint4*)g_Of;
        for (int i = tid; i < 2048; i += NTH) d[6144 + i] = s2[i];
    }
    if (tid < 128) {
        int o = tid & 15, chunk = tid >> 4;
        bns[chunk * 16 + pperm(o)] = bhh[256 + tid];
    }
    __syncthreads();

    const int w = tid >> 5, T = tid & 31;
    const int sub = w & 3, quad = w >> 2;          // quad shares a 16-row tile; sub splits j 4-way
    const int g = T >> 2, a4 = (T & 3) * 4;
    const int rowA = blockIdx.x * 64 + quad * 16 + g;
    const int rowB = rowA + 8;
    const int jbase = sub * 32;                    // own j range: [jbase, jbase+32)
    const float* __restrict__ tab = g_tab;
    const float* bnsw = bns + jbase + a4;
    const uint32_t* Bsw = Bs + sub * 2 * 8 * 32 * 12;

    uint32_t A[32];
    float hp[16];                                  // fp32 h carry for OWN j's only
    #pragma unroll
    for (int i = 0; i < 32; i++) A[i] = 0u;
    #pragma unroll
    for (int i = 0; i < 16; i++) hp[i] = 0.0f;

    int idxA = x[rowA * L_SZ], idxB = x[rowB * L_SZ];
    const float* tA = tab + (size_t)idxA * G3 + jbase + a4;
    const float* tB = tab + (size_t)idxB * G3 + jbase + a4;

    // preload own chunk 0 of step 0
    float4 crA = __ldg((const float4*)(tA));
    float4 crB = __ldg((const float4*)(tB));
    float4 czA = __ldg((const float4*)(tA + 128));
    float4 czB = __ldg((const float4*)(tB + 128));
    float4 cnA = __ldg((const float4*)(tA + 256));
    float4 cnB = __ldg((const float4*)(tB + 256));

    #pragma unroll 1
    for (int t = 0; t < L_SZ; t++) {
        int idxA2 = idxA, idxB2 = idxB;
        if (t + 1 < L_SZ) {
            idxA2 = x[rowA * L_SZ + t + 1];
            idxB2 = x[rowB * L_SZ + t + 1];
        }
        uint4 AnR[2];
        #pragma unroll
        for (int jci = 0; jci < 2; jci++) {        // own 2 chunks; all reg indices static
            float4 bn4 = *(const float4*)(bnsw + jci * 16);
            float d[6][4] = {
                {crA.x, crA.y, crB.x, crB.y}, {crA.z, crA.w, crB.z, crB.w},
                {czA.x, czA.y, czB.x, czB.y}, {czA.z, czA.w, czB.z, czB.w},
                {bn4.x, bn4.y, bn4.x, bn4.y}, {bn4.z, bn4.w, bn4.z, bn4.w}
            };
            float4 xnc_A = cnA, xnc_B = cnB;
            // prefetch next own chunk (wraps into next step)
            if (jci < 1) {
                crA = __ldg((const float4*)(tA + 16));
                crB = __ldg((const float4*)(tB + 16));
                czA = __ldg((const float4*)(tA + 144));
                czB = __ldg((const float4*)(tB + 144));
                cnA = __ldg((const float4*)(tA + 272));
                cnB = __ldg((const float4*)(tB + 272));
            } else {
                tA = tab + (size_t)idxA2 * G3 + jbase + a4;
                tB = tab + (size_t)idxB2 * G3 + jbase + a4;
                crA = __ldg((const float4*)(tA));
                crB = __ldg((const float4*)(tB));
                czA = __ldg((const float4*)(tA + 128));
                czB = __ldg((const float4*)(tB + 128));
                cnA = __ldg((const float4*)(tA + 256));
                cnB = __ldg((const float4*)(tB + 256));
            }

            #pragma unroll
            for (int kc = 0; kc < 8; kc++) {
                const uint4* bp = (const uint4*)(Bsw + ((jci * 8 + kc) * 32 + T) * 12);
                uint4 b0 = bp[0], b1 = bp[1], b2 = bp[2];
                hmma(d[0], &A[kc * 4], b0.x, b0.y);
                hmma(d[1], &A[kc * 4], b0.z, b0.w);
                hmma(d[2], &A[kc * 4], b1.x, b1.y);
                hmma(d[3], &A[kc * 4], b1.z, b1.w);
                hmma(d[4], &A[kc * 4], b2.x, b2.y);
                hmma(d[5], &A[kc * 4], b2.z, b2.w);
            }

            float xn[8] = {xnc_A.x, xnc_A.y, xnc_B.x, xnc_B.y,
                           xnc_A.z, xnc_A.w, xnc_B.z, xnc_B.w};
            float hv[8];
            #pragma unroll
            for (int u = 0; u < 8; u++) {
                int nt = u >> 2, pos = u & 3;
                float r = fsig_fast(d[nt][pos]);
                float z = fsig_fast(d[2 + nt][pos]);
                float n = ftanh_fast(fmaf(r, d[4 + nt][pos], xn[u]));
                float h = fmaf(z, hp[jci * 8 + u] - n, n);
                hp[jci * 8 + u] = h;
                hv[u] = h;
            }
            AnR[jci] = make_uint4(packh2(hv[0], hv[1]), packh2(hv[2], hv[3]),
                                  packh2(hv[4], hv[5]), packh2(hv[6], hv[7]));
        }

        // quad h-exchange: park own 2 fragments, named barrier, read all 8 chunks
        {
            const int p = t & 1;
            uint4* mine = exch + ((p * 16 + w) * 32 + T) * 2;
            mine[0] = AnR[0];
            mine[1] = AnR[1];
            asm volatile("bar.sync %0, 128;" :: "r"(1 + quad) : "memory");
            #pragma unroll
            for (int c = 0; c < 8; c++) {
                uint4 v = exch[((p * 16 + quad * 4 + (c >> 1)) * 32 + T) * 2 + (c & 1)];
                A[c * 4 + 0] = v.x; A[c * 4 + 1] = v.y;
                A[c * 4 + 2] = v.z; A[c * 4 + 3] = v.w;
            }
        }
        idxA = idxA2; idxB = idxB2;
    }

    // output projection (split 4-way: sub covers 4 of 16 f's)
    float od[4][4];
    #pragma unroll
    for (int f = 0; f < 4; f++)
        #pragma unroll
        for (int p = 0; p < 4; p++) od[f][p] = 0.0f;
    #pragma unroll
    for (int kc = 0; kc < 8; kc++) {
        const uint4* op = (const uint4*)(Os + (kc * 32 + T) * 32) + sub * 2;
        uint4 v0 = op[0], v1 = op[1];
        hmma(od[0], &A[kc * 4], v0.x, v0.y);
        hmma(od[1], &A[kc * 4], v0.z, v0.w);
        hmma(od[2], &A[kc * 4], v1.x, v1.y);
        hmma(od[3], &A[kc * 4], v1.z, v1.w);
    }
    const int q2 = (T & 3) * 2;
    #pragma unroll
    for (int f2 = 0; f2 < 4; f2++) {
        const int f = sub * 4 + f2;
        float2 bo = *(const float2*)(bout + f * 8 + q2);
        float2 oA = make_float2(od[f2][0] + bo.x, od[f2][1] + bo.y);
        float2 oB = make_float2(od[f2][2] + bo.x, od[f2][3] + bo.y);
        *(float2*)(out + (size_t)rowA * OUTD + f * 8 + q2) = oA;
        *(float2*)(out + (size_t)rowB * OUTD + f * 8 + q2) = oB;
    }
}

extern "C" void kernel_launch(void* const* d_in, const int* in_sizes, int n_in,
                              void* d_out, int out_size) {
    const int*   x     = (const int*)d_in[0];
    const float* embed = (const float*)d_in[1];
    const float* Wih   = (const float*)d_in[2];
    const float* Whh   = (const float*)d_in[3];
    const float* bih   = (const float*)d_in[4];
    const float* bhh   = (const float*)d_in[5];
    const float* Wout  = (const float*)d_in[6];
    const float* bout  = (const float*)d_in[7];
    float* out = (float*)d_out;

    static bool attr_done = false;
    if (!attr_done) {
        cudaFuncSetAttribute(gru_kernel, cudaFuncAttributeMaxDynamicSharedMemorySize, GRU_SMEM);
        attr_done = true;
    }

    prep_kernel<<<192, 256>>>(Wih, Whh, bih, bhh, Wout);
    table_kernel<<<NVAL, G3>>>(embed);
    gru_kernel<<<B_SZ / 64, NTH, GRU_SMEM>>>(x, bhh, bout, out);
}